// round 6
// baseline (speedup 1.0000x reference)
#include <cuda_runtime.h>
#include <cuda_fp16.h>

#define NWORD  20000
#define NTOPIC 50
#define NDOC   2000
#define NTOT   22050
#define INDIM  256
#define OUTDIM 128
#define NHEAD  8
#define NEDGE  150000
#define UROWS  64150

// ---------------- scratch ----------------
__device__ __align__(16) __half g_kh[NTOT * OUTDIM];
__device__ __align__(16) __half g_qh[NTOT * OUTDIM];
__device__ __align__(16) __half g_vh[NTOT * OUTDIM];
__device__ __align__(16) float g_u[(size_t)UROWS * OUTDIM];   // unnormalized sum(ex*v)
__device__ __align__(16) float g_den[UROWS * NHEAD];          // sum(ex)

// per-etype tables
__constant__ int c_sbase[8] = {0, 0, 20000, 20000, 0, 20000, 20050, 20050};
__constant__ int c_dbase[8] = {20000, 20050, 20050, 20000, 0, 0, 20000, 0};
__constant__ int c_uoff[8]  = {0, 50, 2050, 4050, 4100, 24100, 44100, 44150};
__constant__ int c_topic[8] = {1, 0, 0, 1, 0, 0, 1, 0};
__constant__ int c_elist[3][3] = {{4, 5, 7}, {0, 3, 6}, {1, 2, 0}};
__constant__ int c_nel[3] = {3, 3, 2};

#define BPE 148
#define NWRP (BPE * 8)

// warp partition for the final kernel (4 nodes per warp, ntype-uniform warps)
#define WWORD 5000
#define WTOPIC 13
#define WTOT 5513   // 5000 + 13 + 500

// ---------------- helpers ----------------
__device__ __forceinline__ void ffma2(unsigned long long& d, unsigned long long a,
                                      unsigned long long b) {
    asm("fma.rn.f32x2 %0, %1, %2, %0;" : "+l"(d) : "l"(a), "l"(b));
}
__device__ __forceinline__ unsigned long long pack2(float x) {
    unsigned long long r;
    asm("mov.b64 %0, {%1, %1};" : "=l"(r) : "f"(x));
    return r;
}
__device__ __forceinline__ float2 unpack2(unsigned long long v) {
    float2 f;
    asm("mov.b64 {%0, %1}, %2;" : "=f"(f.x), "=f"(f.y) : "l"(v));
    return f;
}
__device__ __forceinline__ void red_add_v4(float* p, float4 v) {
    asm volatile("red.global.add.v4.f32 [%0], {%1, %2, %3, %4};"
                 :: "l"(p), "f"(v.x), "f"(v.y), "f"(v.z), "f"(v.w) : "memory");
}
__device__ __forceinline__ void red_add_f32(float* p, float v) {
    asm volatile("red.global.add.f32 [%0], %1;" :: "l"(p), "f"(v) : "memory");
}

// ---------------- init: zero u and den ----------------
__global__ void init_all_kernel() {
    int tid = blockIdx.x * blockDim.x + threadIdx.x;
    int nth = gridDim.x * blockDim.x;
    float4 z4 = make_float4(0.f, 0.f, 0.f, 0.f);
    for (size_t i = tid; i < (size_t)UROWS * OUTDIM / 4; i += nth) ((float4*)g_u)[i] = z4;
    for (int i = tid; i < UROWS * NHEAD / 4; i += nth) ((float4*)g_den)[i] = z4;
}

// ---------------- kqv (FFMA2, half output): grid (690 node-tiles, 3 matrices) ----------------
__global__ void kqv_fused_kernel(const float* __restrict__ xw, const float* __restrict__ xt,
                                 const float* __restrict__ xd,
                                 const float* __restrict__ Wk, const float* __restrict__ bk,
                                 const float* __restrict__ Wq, const float* __restrict__ bq,
                                 const float* __restrict__ Wv, const float* __restrict__ bv) {
    __shared__ __align__(16) float xs[32 * INDIM];
    int bx = blockIdx.x;
    int t, n0, N, gbase;
    const float* x;
    if (bx < 625)      { t = 0; n0 = bx * 32;         N = NWORD;  gbase = 0;      x = xw; }
    else if (bx < 627) { t = 1; n0 = (bx - 625) * 32; N = NTOPIC; gbase = NWORD;  x = xt; }
    else               { t = 2; n0 = (bx - 627) * 32; N = NDOC;   gbase = NWORD + NTOPIC; x = xd; }

    int m = blockIdx.y;
    const float* W = (m == 0 ? Wk : (m == 1 ? Wq : Wv)) + (size_t)t * INDIM * OUTDIM;
    const float* bb = (m == 0 ? bk : (m == 1 ? bq : bv)) + t * OUTDIM;
    __half* outp = (m == 0 ? g_kh : (m == 1 ? g_qh : g_vh));

    int tid = threadIdx.x;
    for (int idx = tid; idx < 32 * INDIM; idx += 256) {
        int r = idx >> 8, c = idx & 255;
        int n = n0 + r;
        xs[idx] = (n < N) ? x[(size_t)n * INDIM + c] : 0.0f;
    }
    __syncthreads();

    int ty = tid >> 5, tx = tid & 31;
    int c0 = tx * 4;
    int r0 = ty * 4;

    unsigned long long acc2[4][2];
#pragma unroll
    for (int r = 0; r < 4; r++) { acc2[r][0] = 0ull; acc2[r][1] = 0ull; }

#pragma unroll 4
    for (int kk = 0; kk < INDIM; kk += 4) {
        float4 xv0 = *(const float4*)&xs[(r0 + 0) * INDIM + kk];
        float4 xv1 = *(const float4*)&xs[(r0 + 1) * INDIM + kk];
        float4 xv2 = *(const float4*)&xs[(r0 + 2) * INDIM + kk];
        float4 xv3 = *(const float4*)&xs[(r0 + 3) * INDIM + kk];
        ulonglong2 w0 = __ldg((const ulonglong2*)&W[(kk + 0) * OUTDIM + c0]);
        ulonglong2 w1 = __ldg((const ulonglong2*)&W[(kk + 1) * OUTDIM + c0]);
        ulonglong2 w2 = __ldg((const ulonglong2*)&W[(kk + 2) * OUTDIM + c0]);
        ulonglong2 w3 = __ldg((const ulonglong2*)&W[(kk + 3) * OUTDIM + c0]);
#pragma unroll
        for (int r = 0; r < 4; r++) {
            float4 xv = (r == 0) ? xv0 : (r == 1) ? xv1 : (r == 2) ? xv2 : xv3;
            unsigned long long p0 = pack2(xv.x);
            ffma2(acc2[r][0], p0, w0.x); ffma2(acc2[r][1], p0, w0.y);
            unsigned long long p1 = pack2(xv.y);
            ffma2(acc2[r][0], p1, w1.x); ffma2(acc2[r][1], p1, w1.y);
            unsigned long long p2 = pack2(xv.z);
            ffma2(acc2[r][0], p2, w2.x); ffma2(acc2[r][1], p2, w2.y);
            unsigned long long p3 = pack2(xv.w);
            ffma2(acc2[r][0], p3, w3.x); ffma2(acc2[r][1], p3, w3.y);
        }
    }

    float4 b4 = __ldg((const float4*)&bb[c0]);
#pragma unroll
    for (int r = 0; r < 4; r++) {
        int n = n0 + r0 + r;
        if (n < N) {
            float2 lo = unpack2(acc2[r][0]);
            float2 hi = unpack2(acc2[r][1]);
            union { uint2 u; __half2 h[2]; } pk;
            pk.h[0] = __floats2half2_rn(lo.x + b4.x, lo.y + b4.y);
            pk.h[1] = __floats2half2_rn(hi.x + b4.z, hi.y + b4.w);
            *(uint2*)&outp[(size_t)(gbase + n) * OUTDIM + c0] = pk.u;
        }
    }
}

// ---------------- fused edge pass (half gathers), unroll x4 ----------------
__global__ void __launch_bounds__(256, 3)
edge_fused_kernel(const int* __restrict__ esrc, const int* __restrict__ edst,
                  const float* __restrict__ pri) {
    __shared__ float us[NTOPIC * OUTDIM];   // 25.6 KB
    __shared__ float ds[NTOPIC * NHEAD];    // 1.6 KB
    int e = blockIdx.x / BPE;
    int blk = blockIdx.x - e * BPE;
    bool topic = c_topic[e];
    if (topic) {
        for (int i = threadIdx.x; i < NTOPIC * OUTDIM; i += 256) us[i] = 0.0f;
        for (int i = threadIdx.x; i < NTOPIC * NHEAD; i += 256) ds[i] = 0.0f;
        __syncthreads();
    }
    const int* src = esrc + (size_t)e * NEDGE;
    const int* dst = edst + (size_t)e * NEDGE;
    float* u = g_u + (size_t)c_uoff[e] * OUTDIM;
    float* den = g_den + (size_t)c_uoff[e] * NHEAD;
    int sbase = c_sbase[e], dbase = c_dbase[e];

    int lane = threadIdx.x & 31;
    int h = lane >> 2;
    int w = blk * 8 + (threadIdx.x >> 5);
    float prih = __ldg(&pri[e * NHEAD + h]) * 0.25f;

    for (int base = w; base < NEDGE; base += NWRP * 4) {
        int ss[4], dd[4];
        bool act[4];
        uint2 q2[4], k2[4], v2[4];
#pragma unroll
        for (int j = 0; j < 4; j++) {
            int i = base + j * NWRP;
            act[j] = (i < NEDGE);
            if (act[j]) { ss[j] = __ldg(src + i); dd[j] = __ldg(dst + i); }
        }
#pragma unroll
        for (int j = 0; j < 4; j++) {
            if (act[j]) {
                q2[j] = __ldg((const uint2*)(g_qh + (size_t)(dbase + dd[j]) * OUTDIM) + lane);
                k2[j] = __ldg((const uint2*)(g_kh + (size_t)(sbase + ss[j]) * OUTDIM) + lane);
                v2[j] = __ldg((const uint2*)(g_vh + (size_t)(sbase + ss[j]) * OUTDIM) + lane);
            }
        }
#pragma unroll
        for (int j = 0; j < 4; j++) {
            if (act[j]) {
                float2 qa = __half22float2(*(__half2*)&q2[j].x);
                float2 qb = __half22float2(*(__half2*)&q2[j].y);
                float2 ka = __half22float2(*(__half2*)&k2[j].x);
                float2 kb = __half22float2(*(__half2*)&k2[j].y);
                float p = qa.x * ka.x + qa.y * ka.y + qb.x * kb.x + qb.y * kb.y;
                p += __shfl_xor_sync(0xffffffffu, p, 1);
                p += __shfl_xor_sync(0xffffffffu, p, 2);
                float ex = __expf(p * prih);
                float2 va = __half22float2(*(__half2*)&v2[j].x);
                float2 vb = __half22float2(*(__half2*)&v2[j].y);
                float4 vv = make_float4(va.x * ex, va.y * ex, vb.x * ex, vb.y * ex);
                int d = dd[j];
                if (topic) {
                    float* pp = &us[d * OUTDIM + lane * 4];
                    atomicAdd(pp + 0, vv.x); atomicAdd(pp + 1, vv.y);
                    atomicAdd(pp + 2, vv.z); atomicAdd(pp + 3, vv.w);
                    if ((lane & 3) == 0) atomicAdd(&ds[d * NHEAD + h], ex);
                } else {
                    red_add_v4(&u[(size_t)d * OUTDIM + lane * 4], vv);
                    if ((lane & 3) == 0) red_add_f32(&den[d * NHEAD + h], ex);
                }
            }
        }
    }
    if (topic) {
        __syncthreads();
        for (int i = threadIdx.x; i < NTOPIC * OUTDIM; i += 256)
            if (us[i] != 0.0f) red_add_f32(&u[i], us[i]);
        for (int i = threadIdx.x; i < NTOPIC * NHEAD; i += 256)
            if (ds[i] != 0.0f) red_add_f32(&den[i], ds[i]);
    }
}

// ---------------- fused epilogue + final: 4 nodes/warp, msg hoisted ----------------
__global__ void final_fused_kernel(const float* __restrict__ msg,
                                   const float* __restrict__ gamma,
                                   const float* __restrict__ beta,
                                   float* __restrict__ out) {
    int gwarp = (blockIdx.x * blockDim.x + threadIdx.x) >> 5;
    if (gwarp >= WTOT) return;
    int lane = threadIdx.x & 31;
    int h = lane >> 2, j = lane & 3;

    int t, n0, Nt, gbase;
    if (gwarp < WWORD)               { t = 0; n0 = gwarp * 4;            Nt = NWORD;  gbase = 0; }
    else if (gwarp < WWORD + WTOPIC) { t = 1; n0 = (gwarp - WWORD) * 4;  Nt = NTOPIC; gbase = NWORD; }
    else                             { t = 2; n0 = (gwarp - WWORD - WTOPIC) * 4; Nt = NDOC; gbase = NWORD + NTOPIC; }
    int nel = c_nel[t];
    int nn_max = Nt - n0; if (nn_max > 4) nn_max = 4;

    unsigned long long acc2[4][2];
#pragma unroll
    for (int nn = 0; nn < 4; nn++) { acc2[nn][0] = 0ull; acc2[nn][1] = 0ull; }

#pragma unroll 3
    for (int ei = 0; ei < 3; ei++) {
        if (ei >= nel) break;
        int e = c_elist[t][ei];
        const float* msg_e = msg + (size_t)e * NHEAD * 256;
        ulonglong2 mv[16];
#pragma unroll
        for (int dd = 0; dd < 16; dd++)
            mv[dd] = __ldg((const ulonglong2*)&msg_e[(h * 16 + dd) * 16 + j * 4]);

        int uoff = c_uoff[e];
#pragma unroll
        for (int nn = 0; nn < 4; nn++) {
            if (nn >= nn_max) break;
            size_t row = (size_t)(uoff + n0 + nn);
            float dv = __ldg(&g_den[row * NHEAD + h]);
            float inv = (dv > 0.0f) ? __fdividef(1.0f, dv) : 0.0f;
            const float4* up = (const float4*)(g_u + row * OUTDIM + h * 16);
            float4 u0 = up[0], u1 = up[1], u2 = up[2], u3 = up[3];
            float uu[16] = {u0.x * inv, u0.y * inv, u0.z * inv, u0.w * inv,
                            u1.x * inv, u1.y * inv, u1.z * inv, u1.w * inv,
                            u2.x * inv, u2.y * inv, u2.z * inv, u2.w * inv,
                            u3.x * inv, u3.y * inv, u3.z * inv, u3.w * inv};
#pragma unroll
            for (int dd = 0; dd < 16; dd++) {
                unsigned long long sb = pack2(uu[dd]);
                ffma2(acc2[nn][0], sb, mv[dd].x);
                ffma2(acc2[nn][1], sb, mv[dd].y);
            }
        }
    }

    float invc = (t == 2) ? 0.5f : (1.0f / 3.0f);
    float4 g = __ldg((const float4*)&gamma[t * OUTDIM + lane * 4]);
    float4 b = __ldg((const float4*)&beta[t * OUTDIM + lane * 4]);

#pragma unroll
    for (int nn = 0; nn < 4; nn++) {
        if (nn >= nn_max) break;
        float2 a01 = unpack2(acc2[nn][0]);
        float2 a23 = unpack2(acc2[nn][1]);
        float4 hh;
        hh.x = fmaxf(a01.x * invc, 0.f); hh.y = fmaxf(a01.y * invc, 0.f);
        hh.z = fmaxf(a23.x * invc, 0.f); hh.w = fmaxf(a23.y * invc, 0.f);

        float s = hh.x + hh.y + hh.z + hh.w;
#pragma unroll
        for (int o = 16; o; o >>= 1) s += __shfl_xor_sync(0xffffffffu, s, o);
        float mu = s * (1.0f / 128.0f);

        float dx = hh.x - mu, dy = hh.y - mu, dz = hh.z - mu, dw = hh.w - mu;
        float ssq = dx * dx + dy * dy + dz * dz + dw * dw;
#pragma unroll
        for (int o = 16; o; o >>= 1) ssq += __shfl_xor_sync(0xffffffffu, ssq, o);
        float rstd = rsqrtf(ssq * (1.0f / 128.0f) + 1e-5f);

        float4 o4;
        o4.x = dx * rstd * g.x + b.x;
        o4.y = dy * rstd * g.y + b.y;
        o4.z = dz * rstd * g.z + b.z;
        o4.w = dw * rstd * g.w + b.w;
        *(float4*)&out[(size_t)(gbase + n0 + nn) * OUTDIM + lane * 4] = o4;
    }
}

// ---------------- host ----------------
extern "C" void kernel_launch(void* const* d_in, const int* in_sizes, int n_in,
                              void* d_out, int out_size) {
    const float* xw = (const float*)d_in[0];
    const float* xt = (const float*)d_in[1];
    const float* xd = (const float*)d_in[2];
    const float* Wk = (const float*)d_in[3];
    const float* bk = (const float*)d_in[4];
    const float* Wq = (const float*)d_in[5];
    const float* bq = (const float*)d_in[6];
    const float* Wv = (const float*)d_in[7];
    const float* bv = (const float*)d_in[8];
    const float* pri = (const float*)d_in[9];
    const float* msg = (const float*)d_in[10];
    const float* gamma = (const float*)d_in[11];
    const float* beta = (const float*)d_in[12];
    const int* esrc = (const int*)d_in[13];
    const int* edst = (const int*)d_in[14];
    float* out = (float*)d_out;

    init_all_kernel<<<1184, 256>>>();

    dim3 kqv_grid(690, 3);
    kqv_fused_kernel<<<kqv_grid, 256>>>(xw, xt, xd, Wk, bk, Wq, bq, Wv, bv);

    edge_fused_kernel<<<8 * BPE, 256>>>(esrc, edst, pri);

    final_fused_kernel<<<(WTOT * 32 + 127) / 128, 128>>>(msg, gamma, beta, out);
}

// round 7
// speedup vs baseline: 1.0022x; 1.0022x over previous
#include <cuda_runtime.h>
#include <cuda_fp16.h>

#define NWORD  20000
#define NTOPIC 50
#define NDOC   2000
#define NTOT   22050
#define INDIM  256
#define OUTDIM 128
#define NHEAD  8
#define NEDGE  150000
#define UROWS  64150

// ---------------- scratch ----------------
__device__ __align__(16) __half g_kh[NTOT * OUTDIM];
__device__ __align__(16) __half g_qh[NTOT * OUTDIM];
__device__ __align__(16) __half g_vh[NTOT * OUTDIM];
__device__ __align__(16) float g_u[(size_t)UROWS * OUTDIM];   // unnormalized sum(ex*v)
__device__ __align__(16) float g_den[UROWS * NHEAD];          // sum(ex)

// per-etype tables
__constant__ int c_sbase[8] = {0, 0, 20000, 20000, 0, 20000, 20050, 20050};
__constant__ int c_dbase[8] = {20000, 20050, 20050, 20000, 0, 0, 20000, 0};
__constant__ int c_uoff[8]  = {0, 50, 2050, 4050, 4100, 24100, 44100, 44150};
__constant__ int c_topic[8] = {1, 0, 0, 1, 0, 0, 1, 0};
__constant__ int c_elist[3][3] = {{4, 5, 7}, {0, 3, 6}, {1, 2, 0}};
__constant__ int c_nel[3] = {3, 3, 2};

#define BPE 148
#define NWRP (BPE * 8)

// warp partition for the final kernel (4 nodes per warp, ntype-uniform warps)
#define WWORD 5000
#define WTOPIC 13
#define WTOT 5513   // 5000 + 13 + 500

// ---------------- helpers ----------------
__device__ __forceinline__ void ffma2(unsigned long long& d, unsigned long long a,
                                      unsigned long long b) {
    asm("fma.rn.f32x2 %0, %1, %2, %0;" : "+l"(d) : "l"(a), "l"(b));
}
__device__ __forceinline__ unsigned long long pack2(float x) {
    unsigned long long r;
    asm("mov.b64 %0, {%1, %1};" : "=l"(r) : "f"(x));
    return r;
}
__device__ __forceinline__ float2 unpack2(unsigned long long v) {
    float2 f;
    asm("mov.b64 {%0, %1}, %2;" : "=f"(f.x), "=f"(f.y) : "l"(v));
    return f;
}
__device__ __forceinline__ void red_add_v4(float* p, float4 v) {
    asm volatile("red.global.add.v4.f32 [%0], {%1, %2, %3, %4};"
                 :: "l"(p), "f"(v.x), "f"(v.y), "f"(v.z), "f"(v.w) : "memory");
}
__device__ __forceinline__ void red_add_f32(float* p, float v) {
    asm volatile("red.global.add.f32 [%0], %1;" :: "l"(p), "f"(v) : "memory");
}

// ---------------- init: zero u and den ----------------
__global__ void init_all_kernel() {
    int tid = blockIdx.x * blockDim.x + threadIdx.x;
    int nth = gridDim.x * blockDim.x;
    float4 z4 = make_float4(0.f, 0.f, 0.f, 0.f);
    for (size_t i = tid; i < (size_t)UROWS * OUTDIM / 4; i += nth) ((float4*)g_u)[i] = z4;
    for (int i = tid; i < UROWS * NHEAD / 4; i += nth) ((float4*)g_den)[i] = z4;
}

// ---------------- kqv (FFMA2, half output): grid (690 node-tiles, 3 matrices) ----------------
__global__ void kqv_fused_kernel(const float* __restrict__ xw, const float* __restrict__ xt,
                                 const float* __restrict__ xd,
                                 const float* __restrict__ Wk, const float* __restrict__ bk,
                                 const float* __restrict__ Wq, const float* __restrict__ bq,
                                 const float* __restrict__ Wv, const float* __restrict__ bv) {
    __shared__ __align__(16) float xs[32 * INDIM];
    int bx = blockIdx.x;
    int t, n0, N, gbase;
    const float* x;
    if (bx < 625)      { t = 0; n0 = bx * 32;         N = NWORD;  gbase = 0;      x = xw; }
    else if (bx < 627) { t = 1; n0 = (bx - 625) * 32; N = NTOPIC; gbase = NWORD;  x = xt; }
    else               { t = 2; n0 = (bx - 627) * 32; N = NDOC;   gbase = NWORD + NTOPIC; x = xd; }

    int m = blockIdx.y;
    const float* W = (m == 0 ? Wk : (m == 1 ? Wq : Wv)) + (size_t)t * INDIM * OUTDIM;
    const float* bb = (m == 0 ? bk : (m == 1 ? bq : bv)) + t * OUTDIM;
    __half* outp = (m == 0 ? g_kh : (m == 1 ? g_qh : g_vh));

    int tid = threadIdx.x;
    for (int idx = tid; idx < 32 * INDIM; idx += 256) {
        int r = idx >> 8, c = idx & 255;
        int n = n0 + r;
        xs[idx] = (n < N) ? x[(size_t)n * INDIM + c] : 0.0f;
    }
    __syncthreads();

    int ty = tid >> 5, tx = tid & 31;
    int c0 = tx * 4;
    int r0 = ty * 4;

    unsigned long long acc2[4][2];
#pragma unroll
    for (int r = 0; r < 4; r++) { acc2[r][0] = 0ull; acc2[r][1] = 0ull; }

#pragma unroll 4
    for (int kk = 0; kk < INDIM; kk += 4) {
        float4 xv0 = *(const float4*)&xs[(r0 + 0) * INDIM + kk];
        float4 xv1 = *(const float4*)&xs[(r0 + 1) * INDIM + kk];
        float4 xv2 = *(const float4*)&xs[(r0 + 2) * INDIM + kk];
        float4 xv3 = *(const float4*)&xs[(r0 + 3) * INDIM + kk];
        ulonglong2 w0 = __ldg((const ulonglong2*)&W[(kk + 0) * OUTDIM + c0]);
        ulonglong2 w1 = __ldg((const ulonglong2*)&W[(kk + 1) * OUTDIM + c0]);
        ulonglong2 w2 = __ldg((const ulonglong2*)&W[(kk + 2) * OUTDIM + c0]);
        ulonglong2 w3 = __ldg((const ulonglong2*)&W[(kk + 3) * OUTDIM + c0]);
#pragma unroll
        for (int r = 0; r < 4; r++) {
            float4 xv = (r == 0) ? xv0 : (r == 1) ? xv1 : (r == 2) ? xv2 : xv3;
            unsigned long long p0 = pack2(xv.x);
            ffma2(acc2[r][0], p0, w0.x); ffma2(acc2[r][1], p0, w0.y);
            unsigned long long p1 = pack2(xv.y);
            ffma2(acc2[r][0], p1, w1.x); ffma2(acc2[r][1], p1, w1.y);
            unsigned long long p2 = pack2(xv.z);
            ffma2(acc2[r][0], p2, w2.x); ffma2(acc2[r][1], p2, w2.y);
            unsigned long long p3 = pack2(xv.w);
            ffma2(acc2[r][0], p3, w3.x); ffma2(acc2[r][1], p3, w3.y);
        }
    }

    float4 b4 = __ldg((const float4*)&bb[c0]);
#pragma unroll
    for (int r = 0; r < 4; r++) {
        int n = n0 + r0 + r;
        if (n < N) {
            float2 lo = unpack2(acc2[r][0]);
            float2 hi = unpack2(acc2[r][1]);
            union { uint2 u; __half2 h[2]; } pk;
            pk.h[0] = __floats2half2_rn(lo.x + b4.x, lo.y + b4.y);
            pk.h[1] = __floats2half2_rn(hi.x + b4.z, hi.y + b4.w);
            *(uint2*)&outp[(size_t)(gbase + n) * OUTDIM + c0] = pk.u;
        }
    }
}

// ---------------- fused edge pass (half gathers), unroll x4 ----------------
__global__ void __launch_bounds__(256, 3)
edge_fused_kernel(const int* __restrict__ esrc, const int* __restrict__ edst,
                  const float* __restrict__ pri) {
    __shared__ float us[NTOPIC * OUTDIM];   // 25.6 KB
    __shared__ float ds[NTOPIC * NHEAD];    // 1.6 KB
    int e = blockIdx.x / BPE;
    int blk = blockIdx.x - e * BPE;
    bool topic = c_topic[e];
    if (topic) {
        for (int i = threadIdx.x; i < NTOPIC * OUTDIM; i += 256) us[i] = 0.0f;
        for (int i = threadIdx.x; i < NTOPIC * NHEAD; i += 256) ds[i] = 0.0f;
        __syncthreads();
    }
    const int* src = esrc + (size_t)e * NEDGE;
    const int* dst = edst + (size_t)e * NEDGE;
    float* u = g_u + (size_t)c_uoff[e] * OUTDIM;
    float* den = g_den + (size_t)c_uoff[e] * NHEAD;
    int sbase = c_sbase[e], dbase = c_dbase[e];

    int lane = threadIdx.x & 31;
    int h = lane >> 2;
    int w = blk * 8 + (threadIdx.x >> 5);
    float prih = __ldg(&pri[e * NHEAD + h]) * 0.25f;

    for (int base = w; base < NEDGE; base += NWRP * 4) {
        int ss[4], dd[4];
        bool act[4];
        uint2 q2[4], k2[4], v2[4];
#pragma unroll
        for (int j = 0; j < 4; j++) {
            int i = base + j * NWRP;
            act[j] = (i < NEDGE);
            if (act[j]) { ss[j] = __ldg(src + i); dd[j] = __ldg(dst + i); }
        }
#pragma unroll
        for (int j = 0; j < 4; j++) {
            if (act[j]) {
                q2[j] = __ldg((const uint2*)(g_qh + (size_t)(dbase + dd[j]) * OUTDIM) + lane);
                k2[j] = __ldg((const uint2*)(g_kh + (size_t)(sbase + ss[j]) * OUTDIM) + lane);
                v2[j] = __ldg((const uint2*)(g_vh + (size_t)(sbase + ss[j]) * OUTDIM) + lane);
            }
        }
#pragma unroll
        for (int j = 0; j < 4; j++) {
            if (act[j]) {
                float2 qa = __half22float2(*(__half2*)&q2[j].x);
                float2 qb = __half22float2(*(__half2*)&q2[j].y);
                float2 ka = __half22float2(*(__half2*)&k2[j].x);
                float2 kb = __half22float2(*(__half2*)&k2[j].y);
                float p = qa.x * ka.x + qa.y * ka.y + qb.x * kb.x + qb.y * kb.y;
                p += __shfl_xor_sync(0xffffffffu, p, 1);
                p += __shfl_xor_sync(0xffffffffu, p, 2);
                float ex = __expf(p * prih);
                float2 va = __half22float2(*(__half2*)&v2[j].x);
                float2 vb = __half22float2(*(__half2*)&v2[j].y);
                float4 vv = make_float4(va.x * ex, va.y * ex, vb.x * ex, vb.y * ex);
                int d = dd[j];
                if (topic) {
                    float* pp = &us[d * OUTDIM + lane * 4];
                    atomicAdd(pp + 0, vv.x); atomicAdd(pp + 1, vv.y);
                    atomicAdd(pp + 2, vv.z); atomicAdd(pp + 3, vv.w);
                    if ((lane & 3) == 0) atomicAdd(&ds[d * NHEAD + h], ex);
                } else {
                    red_add_v4(&u[(size_t)d * OUTDIM + lane * 4], vv);
                    if ((lane & 3) == 0) red_add_f32(&den[d * NHEAD + h], ex);
                }
            }
        }
    }
    if (topic) {
        __syncthreads();
        for (int i = threadIdx.x; i < NTOPIC * OUTDIM; i += 256)
            if (us[i] != 0.0f) red_add_f32(&u[i], us[i]);
        for (int i = threadIdx.x; i < NTOPIC * NHEAD; i += 256)
            if (ds[i] != 0.0f) red_add_f32(&den[i], ds[i]);
    }
}

// ---------------- fused epilogue + final: 4 nodes/warp, msg hoisted ----------------
__global__ void final_fused_kernel(const float* __restrict__ msg,
                                   const float* __restrict__ gamma,
                                   const float* __restrict__ beta,
                                   float* __restrict__ out) {
    int gwarp = (blockIdx.x * blockDim.x + threadIdx.x) >> 5;
    if (gwarp >= WTOT) return;
    int lane = threadIdx.x & 31;
    int h = lane >> 2, j = lane & 3;

    int t, n0, Nt, gbase;
    if (gwarp < WWORD)               { t = 0; n0 = gwarp * 4;            Nt = NWORD;  gbase = 0; }
    else if (gwarp < WWORD + WTOPIC) { t = 1; n0 = (gwarp - WWORD) * 4;  Nt = NTOPIC; gbase = NWORD; }
    else                             { t = 2; n0 = (gwarp - WWORD - WTOPIC) * 4; Nt = NDOC; gbase = NWORD + NTOPIC; }
    int nel = c_nel[t];
    int nn_max = Nt - n0; if (nn_max > 4) nn_max = 4;

    unsigned long long acc2[4][2];
#pragma unroll
    for (int nn = 0; nn < 4; nn++) { acc2[nn][0] = 0ull; acc2[nn][1] = 0ull; }

#pragma unroll 3
    for (int ei = 0; ei < 3; ei++) {
        if (ei >= nel) break;
        int e = c_elist[t][ei];
        const float* msg_e = msg + (size_t)e * NHEAD * 256;
        ulonglong2 mv[16];
#pragma unroll
        for (int dd = 0; dd < 16; dd++)
            mv[dd] = __ldg((const ulonglong2*)&msg_e[(h * 16 + dd) * 16 + j * 4]);

        int uoff = c_uoff[e];
#pragma unroll
        for (int nn = 0; nn < 4; nn++) {
            if (nn >= nn_max) break;
            size_t row = (size_t)(uoff + n0 + nn);
            float dv = __ldg(&g_den[row * NHEAD + h]);
            float inv = (dv > 0.0f) ? __fdividef(1.0f, dv) : 0.0f;
            const float4* up = (const float4*)(g_u + row * OUTDIM + h * 16);
            float4 u0 = up[0], u1 = up[1], u2 = up[2], u3 = up[3];
            float uu[16] = {u0.x * inv, u0.y * inv, u0.z * inv, u0.w * inv,
                            u1.x * inv, u1.y * inv, u1.z * inv, u1.w * inv,
                            u2.x * inv, u2.y * inv, u2.z * inv, u2.w * inv,
                            u3.x * inv, u3.y * inv, u3.z * inv, u3.w * inv};
#pragma unroll
            for (int dd = 0; dd < 16; dd++) {
                unsigned long long sb = pack2(uu[dd]);
                ffma2(acc2[nn][0], sb, mv[dd].x);
                ffma2(acc2[nn][1], sb, mv[dd].y);
            }
        }
    }

    float invc = (t == 2) ? 0.5f : (1.0f / 3.0f);
    float4 g = __ldg((const float4*)&gamma[t * OUTDIM + lane * 4]);
    float4 b = __ldg((const float4*)&beta[t * OUTDIM + lane * 4]);

#pragma unroll
    for (int nn = 0; nn < 4; nn++) {
        if (nn >= nn_max) break;
        float2 a01 = unpack2(acc2[nn][0]);
        float2 a23 = unpack2(acc2[nn][1]);
        float4 hh;
        hh.x = fmaxf(a01.x * invc, 0.f); hh.y = fmaxf(a01.y * invc, 0.f);
        hh.z = fmaxf(a23.x * invc, 0.f); hh.w = fmaxf(a23.y * invc, 0.f);

        float s = hh.x + hh.y + hh.z + hh.w;
#pragma unroll
        for (int o = 16; o; o >>= 1) s += __shfl_xor_sync(0xffffffffu, s, o);
        float mu = s * (1.0f / 128.0f);

        float dx = hh.x - mu, dy = hh.y - mu, dz = hh.z - mu, dw = hh.w - mu;
        float ssq = dx * dx + dy * dy + dz * dz + dw * dw;
#pragma unroll
        for (int o = 16; o; o >>= 1) ssq += __shfl_xor_sync(0xffffffffu, ssq, o);
        float rstd = rsqrtf(ssq * (1.0f / 128.0f) + 1e-5f);

        float4 o4;
        o4.x = dx * rstd * g.x + b.x;
        o4.y = dy * rstd * g.y + b.y;
        o4.z = dz * rstd * g.z + b.z;
        o4.w = dw * rstd * g.w + b.w;
        *(float4*)&out[(size_t)(gbase + n0 + nn) * OUTDIM + lane * 4] = o4;
    }
}

// ---------------- host ----------------
extern "C" void kernel_launch(void* const* d_in, const int* in_sizes, int n_in,
                              void* d_out, int out_size) {
    const float* xw = (const float*)d_in[0];
    const float* xt = (const float*)d_in[1];
    const float* xd = (const float*)d_in[2];
    const float* Wk = (const float*)d_in[3];
    const float* bk = (const float*)d_in[4];
    const float* Wq = (const float*)d_in[5];
    const float* bq = (const float*)d_in[6];
    const float* Wv = (const float*)d_in[7];
    const float* bv = (const float*)d_in[8];
    const float* pri = (const float*)d_in[9];
    const float* msg = (const float*)d_in[10];
    const float* gamma = (const float*)d_in[11];
    const float* beta = (const float*)d_in[12];
    const int* esrc = (const int*)d_in[13];
    const int* edst = (const int*)d_in[14];
    float* out = (float*)d_out;

    init_all_kernel<<<1184, 256>>>();

    dim3 kqv_grid(690, 3);
    kqv_fused_kernel<<<kqv_grid, 256>>>(xw, xt, xd, Wk, bk, Wq, bq, Wv, bv);

    edge_fused_kernel<<<8 * BPE, 256>>>(esrc, edst, pri);

    final_fused_kernel<<<(WTOT * 32 + 127) / 128, 128>>>(msg, gamma, beta, out);
}